// round 1
// baseline (speedup 1.0000x reference)
#include <cuda_runtime.h>
#include <cuda_bf16.h>

// WindowAttention: B_=8192 windows, N=64 tokens, C=96, H=6 heads, hd=16.
// One CTA per window, 384 threads.
// Phases: [load x] -> [qkv GEMM] -> [attention (bias+mask+softmax+PV)] -> [proj GEMM]

#define THREADS 384
#define N_TOK   64
#define DIM     96
#define HEADS   6
#define HD      16
#define XPAD    97   // row pad for smem matrices (97 mod 32 == 1 -> conflict-friendly)

// smem layout (floats):
//  xs   [64*97]      = 6208   (x, later attention output)
//  qs   [192*97]     = 18624  (q|k|v rows 0..63 / 64..127 / 128..191; later proj_w[96*96])
//  ws   [8*288]      = 2304   (qkv weight k-chunk)
//  ridx [64*64] int  = 4096   (rel_index, transposed: [m*64+n])
//  msk  [64*64]      = 4096   (mask slice, transposed: [m*64+n])
#define XS_OFF   0
#define QS_OFF   6208
#define WS_OFF   (6208 + 18624)
#define RIDX_OFF (WS_OFF + 2304)
#define MSK_OFF  (RIDX_OFF + 4096)
#define SMEM_FLOATS (MSK_OFF + 4096)
#define SMEM_BYTES  (SMEM_FLOATS * 4)

extern __shared__ float smem[];

__global__ void __launch_bounds__(THREADS, 1)
win_attn_kernel(const float* __restrict__ x,
                const float* __restrict__ mask,
                const float* __restrict__ qkv_w,
                const float* __restrict__ qkv_b,
                const float* __restrict__ proj_w,
                const float* __restrict__ proj_b,
                const float* __restrict__ rpb,
                const int*   __restrict__ ridx,
                float* __restrict__ out,
                int nW)
{
    float* xs = smem + XS_OFF;
    float* qs = smem + QS_OFF;
    float* ws = smem + WS_OFF;
    int*   rs = (int*)(smem + RIDX_OFF);
    float* ms = smem + MSK_OFF;

    const int t = threadIdx.x;
    const int b = blockIdx.x;
    const float* xb = x + (size_t)b * (N_TOK * DIM);
    const float* mb = mask + (size_t)(b % nW) * (N_TOK * N_TOK);

    // ---- stage x (coalesced), rel_index + mask (transposed so attention reads are stride-1) ----
    #pragma unroll
    for (int i = 0; i < 16; i++) {
        int idx = t + i * THREADS;          // 6144 elems
        xs[(idx / DIM) * XPAD + (idx % DIM)] = xb[idx];
    }
    #pragma unroll
    for (int i = 0; i < 11; i++) {
        int st = t + i * THREADS;           // 4096 elems
        if (st < N_TOK * N_TOK) {
            int gidx = ((st & 63) << 6) | (st >> 6);  // transpose: smem[m*64+n] = g[n*64+m]
            rs[st] = ridx[gidx];
            ms[st] = mb[gidx];
        }
    }
    __syncthreads();

    // ---- qkv GEMM: (64x96) @ (96x288) + b.  4 rows x 12 cols per thread ----
    {
        const int tr = t & 15;       // row group: rows 4*tr .. 4*tr+3
        const int tc = t >> 4;       // col group: cols 12*tc .. 12*tc+11 (0..287)
        const int s  = tc >> 3;      // 0=q,1=k,2=v (12*8 = 96 cols per matrix, exact split)
        float acc[4][12];
        #pragma unroll
        for (int j = 0; j < 12; j++) {
            float bv = qkv_b[tc * 12 + j];
            #pragma unroll
            for (int i = 0; i < 4; i++) acc[i][j] = bv;
        }
        for (int kc = 0; kc < 12; kc++) {
            int k0 = kc * 8;
            #pragma unroll
            for (int i = 0; i < 6; i++) {
                int idx = t + i * THREADS;   // 2304 elems
                ws[idx] = qkv_w[k0 * 288 + idx];
            }
            __syncthreads();
            #pragma unroll
            for (int kk = 0; kk < 8; kk++) {
                float xa[4], wb[12];
                #pragma unroll
                for (int i = 0; i < 4; i++) xa[i] = xs[(tr * 4 + i) * XPAD + k0 + kk];
                #pragma unroll
                for (int j = 0; j < 12; j++) wb[j] = ws[kk * 288 + tc * 12 + j];
                #pragma unroll
                for (int i = 0; i < 4; i++)
                    #pragma unroll
                    for (int j = 0; j < 12; j++)
                        acc[i][j] = fmaf(xa[i], wb[j], acc[i][j]);
            }
            __syncthreads();
        }
        #pragma unroll
        for (int j = 0; j < 12; j++) {
            int c  = tc * 12 + j;
            int cc = c - s * DIM;
            #pragma unroll
            for (int i = 0; i < 4; i++)
                qs[(s * N_TOK + tr * 4 + i) * XPAD + cc] = acc[i][j];
        }
    }
    __syncthreads();

    // ---- attention: thread = (head h, query row n) ----
    {
        const int h = t / N_TOK;     // 0..5
        const int n = t & 63;        // 0..63
        const float scale = 0.25f;   // hd^-0.5 = 16^-0.5

        float qv[HD];
        #pragma unroll
        for (int d = 0; d < HD; d++) qv[d] = qs[n * XPAD + h * HD + d];

        const float* kbase = qs + N_TOK * XPAD + h * HD;       // k rows
        const float* vbase = qs + 2 * N_TOK * XPAD + h * HD;   // v rows

        float sc[N_TOK];
        float mx = -1e30f;
        #pragma unroll
        for (int m = 0; m < N_TOK; m++) {
            const float* kr = kbase + m * XPAD;   // whole warp: same address -> broadcast
            float d0 = 0.f;
            #pragma unroll
            for (int d = 0; d < HD; d++) d0 = fmaf(qv[d], kr[d], d0);
            float bias = rpb[rs[m * 64 + n] * HEADS + h];  // stride-1 smem idx, L1 table gather
            float v = fmaf(d0, scale, bias) + ms[m * 64 + n];
            sc[m] = v;
            mx = fmaxf(mx, v);
        }
        float sum = 0.f;
        #pragma unroll
        for (int m = 0; m < N_TOK; m++) {
            float e = __expf(sc[m] - mx);
            sc[m] = e;
            sum += e;
        }
        float inv = 1.f / sum;

        float acc[HD];
        #pragma unroll
        for (int d = 0; d < HD; d++) acc[d] = 0.f;
        #pragma unroll
        for (int m = 0; m < N_TOK; m++) {
            float p = sc[m];
            const float* vr = vbase + m * XPAD;   // broadcast
            #pragma unroll
            for (int d = 0; d < HD; d++) acc[d] = fmaf(p, vr[d], acc[d]);
        }
        // write attention output into xs (x no longer needed)
        #pragma unroll
        for (int d = 0; d < HD; d++) xs[n * XPAD + h * HD + d] = acc[d] * inv;
    }
    __syncthreads();

    // ---- stage proj_w (96x96) into qs region (q/k/v no longer needed) ----
    #pragma unroll
    for (int i = 0; i < 24; i++) {
        int idx = t + i * THREADS;   // 9216 elems
        qs[idx] = proj_w[idx];
    }
    __syncthreads();

    // ---- proj GEMM: (64x96) @ (96x96) + b.  thread = (col c, 16-row group) ----
    {
        const int c  = t % DIM;      // 0..95
        const int rg = t / DIM;      // 0..3 -> rows rg*16 .. rg*16+15
        float acc[16];
        float bv = proj_b[c];
        #pragma unroll
        for (int i = 0; i < 16; i++) acc[i] = bv;
        #pragma unroll 8
        for (int k = 0; k < DIM; k++) {
            float wv = qs[k * DIM + c];
            #pragma unroll
            for (int i = 0; i < 16; i++)
                acc[i] = fmaf(xs[(rg * 16 + i) * XPAD + k], wv, acc[i]);
        }
        float* ob = out + (size_t)b * (N_TOK * DIM);
        #pragma unroll
        for (int i = 0; i < 16; i++)
            ob[(rg * 16 + i) * DIM + c] = acc[i];
    }
}

extern "C" void kernel_launch(void* const* d_in, const int* in_sizes, int n_in,
                              void* d_out, int out_size) {
    const float* x      = (const float*)d_in[0];
    const float* mask   = (const float*)d_in[1];
    const float* qkv_w  = (const float*)d_in[2];
    const float* qkv_b  = (const float*)d_in[3];
    const float* proj_w = (const float*)d_in[4];
    const float* proj_b = (const float*)d_in[5];
    const float* rpb    = (const float*)d_in[6];
    const int*   ridx   = (const int*)d_in[7];
    float* out = (float*)d_out;

    const int B_ = in_sizes[0] / (N_TOK * DIM);        // 8192
    const int nW = in_sizes[1] / (N_TOK * N_TOK);      // 512

    cudaFuncSetAttribute(win_attn_kernel,
                         cudaFuncAttributeMaxDynamicSharedMemorySize, SMEM_BYTES);
    win_attn_kernel<<<B_, THREADS, SMEM_BYTES>>>(
        x, mask, qkv_w, qkv_b, proj_w, proj_b, rpb, ridx, out, nW);
}

// round 2
// speedup vs baseline: 1.2734x; 1.2734x over previous
#include <cuda_runtime.h>
#include <cuda_bf16.h>

// WindowAttention: B_=8192 windows, N=64 tokens, C=96, H=6 heads, hd=16.
// One CTA per window, 384 threads. All smem traffic vectorized to float4.

#define THREADS 384
#define N_TOK   64
#define DIM     96
#define HEADS   6
#define HD      16
#define XPAD    100   // row pad (mult of 4 for float4; lane stride 100 mod 32 = 4 -> conflict-free)
#define MPAD    65    // mask/ridx row pad (65 mod 32 = 1 -> conflict-free column reads)

// smem layout (float offsets)
#define XS_OFF   0                         // 64  x 100 = 6400   (x, later attention out)
#define QS_OFF   6400                      // 192 x 100 = 19200  (q|k|v, later proj_w 96x96)
#define WS_OFF   25600                     // 2 x 4608 = 9216    (qkv weight chunk, double buf)
#define RS_OFF   34816                     // 64 x 65 = 4160 (int)
#define MS_OFF   38976                     // 64 x 65 = 4160
#define RPB_OFF  43136                     // 343*6 = 2058
#define SMEM_FLOATS (RPB_OFF + 2058)       // 45194
#define SMEM_BYTES  (SMEM_FLOATS * 4)      // 180776 B

extern __shared__ float smem[];

__global__ void __launch_bounds__(THREADS, 1)
win_attn_kernel(const float* __restrict__ x,
                const float* __restrict__ mask,
                const float* __restrict__ qkv_w,
                const float* __restrict__ qkv_b,
                const float* __restrict__ proj_w,
                const float* __restrict__ proj_b,
                const float* __restrict__ rpb,
                const int*   __restrict__ ridx,
                float* __restrict__ out,
                int nW)
{
    float* xs  = smem + XS_OFF;
    float* qs  = smem + QS_OFF;
    float* ws  = smem + WS_OFF;
    int*   rs_ = (int*)(smem + RS_OFF);
    float* ms_ = smem + MS_OFF;
    float* rpb_s = smem + RPB_OFF;

    const int t = threadIdx.x;
    const int b = blockIdx.x;
    const float* xb = x + (size_t)b * (N_TOK * DIM);
    const float* mb = mask + (size_t)(b % nW) * (N_TOK * N_TOK);

    // ---- stage x (float4, coalesced) ----
    {
        const float4* g = (const float4*)xb;
        #pragma unroll
        for (int j = 0; j < 4; j++) {
            int idx = t + j * THREADS;              // 1536 float4
            int row = idx / 24, col = idx % 24;     // 24 float4 per 96-col row
            *(float4*)&xs[row * XPAD + col * 4] = g[idx];
        }
    }
    // ---- stage rel_index + mask (natural layout, pad 65) ----
    #pragma unroll
    for (int j = 0; j < 11; j++) {
        int st = t + j * THREADS;                   // 4096 elems
        if (st < N_TOK * N_TOK) {
            int n = st >> 6, m = st & 63;
            rs_[n * MPAD + m] = ridx[st];
            ms_[n * MPAD + m] = mb[st];
        }
    }
    // ---- stage rpb table (343*6 floats) ----
    #pragma unroll
    for (int j = 0; j < 6; j++) {
        int idx = t + j * THREADS;
        if (idx < 343 * HEADS) rpb_s[idx] = rpb[idx];
    }
    // ---- stage qkv weight chunk 0 (k rows 0..15) ----
    {
        const float4* g = (const float4*)qkv_w;
        float4* s = (float4*)ws;
        #pragma unroll
        for (int j = 0; j < 3; j++) s[t + j * THREADS] = g[t + j * THREADS];
    }
    __syncthreads();

    // ---- qkv GEMM: (64x96)@(96x288)+b. rows tr+16i, cols tc*12..+11 ----
    {
        const int tr = t & 15;
        const int tc = t >> 4;                      // 0..23
        float acc[4][12];
        #pragma unroll
        for (int j = 0; j < 12; j++) {
            float bv = qkv_b[tc * 12 + j];
            #pragma unroll
            for (int i = 0; i < 4; i++) acc[i][j] = bv;
        }

        #pragma unroll 1
        for (int kc = 0; kc < 6; kc++) {
            // prefetch next chunk into other buffer
            if (kc < 5) {
                const float4* g = (const float4*)(qkv_w + (kc + 1) * 16 * 288);
                float4* s = (float4*)(ws + ((kc + 1) & 1) * 4608);
                #pragma unroll
                for (int j = 0; j < 3; j++) s[t + j * THREADS] = g[t + j * THREADS];
            }
            const float* wsb = ws + (kc & 1) * 4608;
            const int k0 = kc * 16;

            #pragma unroll
            for (int kk = 0; kk < 16; kk += 4) {
                float xr[4][4];
                #pragma unroll
                for (int i = 0; i < 4; i++) {
                    float4 v = *(const float4*)&xs[(tr + 16 * i) * XPAD + k0 + kk];
                    xr[i][0] = v.x; xr[i][1] = v.y; xr[i][2] = v.z; xr[i][3] = v.w;
                }
                #pragma unroll
                for (int kq = 0; kq < 4; kq++) {
                    const float* wrow = wsb + (kk + kq) * 288 + tc * 12;
                    float4 w0 = *(const float4*)(wrow);
                    float4 w1 = *(const float4*)(wrow + 4);
                    float4 w2 = *(const float4*)(wrow + 8);
                    #pragma unroll
                    for (int i = 0; i < 4; i++) {
                        float xv = xr[i][kq];
                        acc[i][0]  = fmaf(xv, w0.x, acc[i][0]);
                        acc[i][1]  = fmaf(xv, w0.y, acc[i][1]);
                        acc[i][2]  = fmaf(xv, w0.z, acc[i][2]);
                        acc[i][3]  = fmaf(xv, w0.w, acc[i][3]);
                        acc[i][4]  = fmaf(xv, w1.x, acc[i][4]);
                        acc[i][5]  = fmaf(xv, w1.y, acc[i][5]);
                        acc[i][6]  = fmaf(xv, w1.z, acc[i][6]);
                        acc[i][7]  = fmaf(xv, w1.w, acc[i][7]);
                        acc[i][8]  = fmaf(xv, w2.x, acc[i][8]);
                        acc[i][9]  = fmaf(xv, w2.y, acc[i][9]);
                        acc[i][10] = fmaf(xv, w2.z, acc[i][10]);
                        acc[i][11] = fmaf(xv, w2.w, acc[i][11]);
                    }
                }
            }
            __syncthreads();
        }

        // write q|k|v to qs (float4 stores)
        const int s  = tc / 8;                      // 0=q,1=k,2=v
        const int cc0 = tc * 12 - s * DIM;          // 0..84, mult of 4
        #pragma unroll
        for (int i = 0; i < 4; i++) {
            float* dst = qs + (s * N_TOK + tr + 16 * i) * XPAD + cc0;
            *(float4*)(dst)     = make_float4(acc[i][0], acc[i][1], acc[i][2],  acc[i][3]);
            *(float4*)(dst + 4) = make_float4(acc[i][4], acc[i][5], acc[i][6],  acc[i][7]);
            *(float4*)(dst + 8) = make_float4(acc[i][8], acc[i][9], acc[i][10], acc[i][11]);
        }
    }
    __syncthreads();

    // ---- attention: thread = (head h, query row n) ----
    {
        const int h = t >> 6;                       // 0..5 (warp-uniform)
        const int n = t & 63;
        const float scale = 0.25f;

        float qv[HD];
        {
            const float4* qp = (const float4*)(qs + n * XPAD + h * HD);
            #pragma unroll
            for (int j = 0; j < 4; j++) {
                float4 v = qp[j];
                qv[j*4+0] = v.x; qv[j*4+1] = v.y; qv[j*4+2] = v.z; qv[j*4+3] = v.w;
            }
        }

        float sc[N_TOK];
        float mx = -1e30f;
        #pragma unroll
        for (int m = 0; m < N_TOK; m++) {
            const float4* kr = (const float4*)(qs + (N_TOK + m) * XPAD + h * HD); // broadcast
            float4 k0 = kr[0], k1 = kr[1], k2 = kr[2], k3 = kr[3];
            float d0 = qv[0]*k0.x + qv[1]*k0.y;
            d0 = fmaf(qv[2],  k0.z, d0); d0 = fmaf(qv[3],  k0.w, d0);
            d0 = fmaf(qv[4],  k1.x, d0); d0 = fmaf(qv[5],  k1.y, d0);
            d0 = fmaf(qv[6],  k1.z, d0); d0 = fmaf(qv[7],  k1.w, d0);
            d0 = fmaf(qv[8],  k2.x, d0); d0 = fmaf(qv[9],  k2.y, d0);
            d0 = fmaf(qv[10], k2.z, d0); d0 = fmaf(qv[11], k2.w, d0);
            d0 = fmaf(qv[12], k3.x, d0); d0 = fmaf(qv[13], k3.y, d0);
            d0 = fmaf(qv[14], k3.z, d0); d0 = fmaf(qv[15], k3.w, d0);
            float bias = rpb_s[rs_[n * MPAD + m] * HEADS + h];
            float val = fmaf(d0, scale, bias) + ms_[n * MPAD + m];
            sc[m] = val;
            mx = fmaxf(mx, val);
        }
        float sum = 0.f;
        #pragma unroll
        for (int m = 0; m < N_TOK; m++) {
            float e = __expf(sc[m] - mx);
            sc[m] = e;
            sum += e;
        }
        float inv = 1.f / sum;

        float acc[HD];
        #pragma unroll
        for (int d = 0; d < HD; d++) acc[d] = 0.f;
        #pragma unroll
        for (int m = 0; m < N_TOK; m++) {
            float p = sc[m];
            const float4* vr = (const float4*)(qs + (2 * N_TOK + m) * XPAD + h * HD); // broadcast
            float4 v0 = vr[0], v1 = vr[1], v2 = vr[2], v3 = vr[3];
            acc[0]  = fmaf(p, v0.x, acc[0]);  acc[1]  = fmaf(p, v0.y, acc[1]);
            acc[2]  = fmaf(p, v0.z, acc[2]);  acc[3]  = fmaf(p, v0.w, acc[3]);
            acc[4]  = fmaf(p, v1.x, acc[4]);  acc[5]  = fmaf(p, v1.y, acc[5]);
            acc[6]  = fmaf(p, v1.z, acc[6]);  acc[7]  = fmaf(p, v1.w, acc[7]);
            acc[8]  = fmaf(p, v2.x, acc[8]);  acc[9]  = fmaf(p, v2.y, acc[9]);
            acc[10] = fmaf(p, v2.z, acc[10]); acc[11] = fmaf(p, v2.w, acc[11]);
            acc[12] = fmaf(p, v3.x, acc[12]); acc[13] = fmaf(p, v3.y, acc[13]);
            acc[14] = fmaf(p, v3.z, acc[14]); acc[15] = fmaf(p, v3.w, acc[15]);
        }
        // write attention output into xs
        float* dst = xs + n * XPAD + h * HD;
        #pragma unroll
        for (int j = 0; j < 4; j++)
            *(float4*)(dst + j * 4) = make_float4(acc[j*4+0] * inv, acc[j*4+1] * inv,
                                                  acc[j*4+2] * inv, acc[j*4+3] * inv);
    }
    __syncthreads();

    // ---- stage proj_w (96x96) into qs (linear) ----
    {
        const float4* g = (const float4*)proj_w;
        float4* s = (float4*)qs;
        #pragma unroll
        for (int j = 0; j < 6; j++) s[t + j * THREADS] = g[t + j * THREADS];  // 2304 f4
    }
    __syncthreads();

    // ---- proj GEMM: (64x96)@(96x96)+b. thread = (4 cols, 4 rows) ----
    {
        const int cg = t % 24;                      // cols cg*4..cg*4+3
        const int rg = t / 24;                      // rows rg*4..rg*4+3
        float4 pb = *(const float4*)(proj_b + cg * 4);
        float acc[4][4];
        #pragma unroll
        for (int i = 0; i < 4; i++) {
            acc[i][0] = pb.x; acc[i][1] = pb.y; acc[i][2] = pb.z; acc[i][3] = pb.w;
        }
        #pragma unroll 6
        for (int k = 0; k < DIM; k += 4) {
            float xr[4][4];
            #pragma unroll
            for (int i = 0; i < 4; i++) {
                float4 v = *(const float4*)&xs[(rg * 4 + i) * XPAD + k];
                xr[i][0] = v.x; xr[i][1] = v.y; xr[i][2] = v.z; xr[i][3] = v.w;
            }
            #pragma unroll
            for (int kq = 0; kq < 4; kq++) {
                float4 wv = *(const float4*)&qs[(k + kq) * DIM + cg * 4];
                #pragma unroll
                for (int i = 0; i < 4; i++) {
                    float xv = xr[i][kq];
                    acc[i][0] = fmaf(xv, wv.x, acc[i][0]);
                    acc[i][1] = fmaf(xv, wv.y, acc[i][1]);
                    acc[i][2] = fmaf(xv, wv.z, acc[i][2]);
                    acc[i][3] = fmaf(xv, wv.w, acc[i][3]);
                }
            }
        }
        float* ob = out + (size_t)b * (N_TOK * DIM);
        #pragma unroll
        for (int i = 0; i < 4; i++)
            *(float4*)&ob[(rg * 4 + i) * DIM + cg * 4] =
                make_float4(acc[i][0], acc[i][1], acc[i][2], acc[i][3]);
    }
}

extern "C" void kernel_launch(void* const* d_in, const int* in_sizes, int n_in,
                              void* d_out, int out_size) {
    const float* x      = (const float*)d_in[0];
    const float* mask   = (const float*)d_in[1];
    const float* qkv_w  = (const float*)d_in[2];
    const float* qkv_b  = (const float*)d_in[3];
    const float* proj_w = (const float*)d_in[4];
    const float* proj_b = (const float*)d_in[5];
    const float* rpb    = (const float*)d_in[6];
    const int*   ridx   = (const int*)d_in[7];
    float* out = (float*)d_out;

    const int B_ = in_sizes[0] / (N_TOK * DIM);        // 8192
    const int nW = in_sizes[1] / (N_TOK * N_TOK);      // 512

    cudaFuncSetAttribute(win_attn_kernel,
                         cudaFuncAttributeMaxDynamicSharedMemorySize, SMEM_BYTES);
    win_attn_kernel<<<B_, THREADS, SMEM_BYTES>>>(
        x, mask, qkv_w, qkv_b, proj_w, proj_b, rpb, ridx, out, nW);
}